// round 1
// baseline (speedup 1.0000x reference)
#include <cuda_runtime.h>

#define HID 128
#define SDIM 3
#define ADIM 2

__device__ __forceinline__ float relu_(float v) { return v > 0.0f ? v : 0.0f; }

__global__ __launch_bounds__(128, 3)
void dyn_reward_kernel(const float* __restrict__ s,
                       const float* __restrict__ a,
                       const float* __restrict__ W1,
                       const float* __restrict__ b1,
                       const float* __restrict__ W2,
                       const float* __restrict__ b2,
                       const float* __restrict__ W3,
                       const float* __restrict__ b3,
                       float* __restrict__ out,
                       int B)
{
    int i = blockIdx.x * blockDim.x + threadIdx.x;
    if (i >= B) return;

    // ---- inputs for this row ----
    const float x0 = s[3 * i + 0];
    const float x1 = s[3 * i + 1];
    const float x2 = s[3 * i + 2];
    const float a0 = a[2 * i + 0];
    const float a1 = a[2 * i + 1];

    // ---- layer 1: x(5) @ W1(5x128) + b1, relu.  h1 lives in registers ----
    float h1[HID];
#pragma unroll
    for (int j = 0; j < HID; j += 4) {
        float4 bb = *(const float4*)(b1 + j);
        float4 w0 = *(const float4*)(W1 + 0 * HID + j);
        float4 w1 = *(const float4*)(W1 + 1 * HID + j);
        float4 w2 = *(const float4*)(W1 + 2 * HID + j);
        float4 w3 = *(const float4*)(W1 + 3 * HID + j);
        float4 w4 = *(const float4*)(W1 + 4 * HID + j);
        h1[j + 0] = relu_(bb.x + x0 * w0.x + x1 * w1.x + x2 * w2.x + a0 * w3.x + a1 * w4.x);
        h1[j + 1] = relu_(bb.y + x0 * w0.y + x1 * w1.y + x2 * w2.y + a0 * w3.y + a1 * w4.y);
        h1[j + 2] = relu_(bb.z + x0 * w0.z + x1 * w1.z + x2 * w2.z + a0 * w3.z + a1 * w4.z);
        h1[j + 3] = relu_(bb.w + x0 * w0.w + x1 * w1.w + x2 * w2.w + a0 * w3.w + a1 * w4.w);
    }

    // ---- layer 2 (128x128) fused with layer 3 (128x3) ----
    float sn0 = b3[0];
    float sn1 = b3[1];
    float sn2 = b3[2];

#pragma unroll 1
    for (int j = 0; j < HID; j += 4) {
        float4 bb = *(const float4*)(b2 + j);
        float acc0 = bb.x, acc1 = bb.y, acc2 = bb.z, acc3 = bb.w;
#pragma unroll
        for (int k = 0; k < HID; k++) {
            float4 w = *(const float4*)(W2 + k * HID + j);
            float hk = h1[k];
            acc0 = fmaf(hk, w.x, acc0);
            acc1 = fmaf(hk, w.y, acc1);
            acc2 = fmaf(hk, w.z, acc2);
            acc3 = fmaf(hk, w.w, acc3);
        }
        acc0 = relu_(acc0);
        acc1 = relu_(acc1);
        acc2 = relu_(acc2);
        acc3 = relu_(acc3);

        // layer 3: W3 is (128, 3) row-major
        const float* w3r = W3 + j * 3;
        sn0 = fmaf(acc0, w3r[0], sn0);
        sn1 = fmaf(acc0, w3r[1], sn1);
        sn2 = fmaf(acc0, w3r[2], sn2);
        sn0 = fmaf(acc1, w3r[3], sn0);
        sn1 = fmaf(acc1, w3r[4], sn1);
        sn2 = fmaf(acc1, w3r[5], sn2);
        sn0 = fmaf(acc2, w3r[6], sn0);
        sn1 = fmaf(acc2, w3r[7], sn1);
        sn2 = fmaf(acc2, w3r[8], sn2);
        sn0 = fmaf(acc3, w3r[9], sn0);
        sn1 = fmaf(acc3, w3r[10], sn1);
        sn2 = fmaf(acc3, w3r[11], sn2);
    }

    // ---- reward (independent of the MLP; uses s[:2] and a) ----
    const float VAR = 0.035f;
    const float SIG = 0.03f;
    const float TWO_PI = 6.283185307179586f;

    // obstacle mixture
    const float obs_x[6] = {0.f, 0.f, 0.f, 0.f, 0.f, -0.8f};
    const float obs_y[6] = {0.f, 0.2f, 0.4f, 0.6f, 0.8f, -0.8f};
    float gsum = 0.0f;
#pragma unroll
    for (int o = 0; o < 6; o++) {
        float dx = x0 - obs_x[o];
        float dy = x1 - obs_y[o];
        float e = -0.5f * (dx * dx + dy * dy) / VAR;
        gsum += expf(e);
    }
    float gauss_sum = 100.0f * gsum / (TWO_PI * VAR);

    float qx = x0 - a0;
    float qy = x1 - a1;
    float quad = 30.0f * (qx * qx + qy * qy);

    float coef = 1.0f / (SIG * sqrtf(TWO_PI));
    float t0 = (x0 + 1.5f) / SIG;
    float t1 = (x0 - 1.5f) / SIG;
    float t2 = (x1 - 1.0f) / SIG;
    float t3 = (x1 + 1.0f) / SIG;
    float bound = 10.0f * coef * (expf(-0.5f * t0 * t0) + expf(-0.5f * t1 * t1) +
                                  expf(-0.5f * t2 * t2) + expf(-0.5f * t3 * t3));

    float r = -(quad + gauss_sum + bound);

    // ---- outputs: s_next (B,3) then r (B,1), concatenated flat ----
    out[3 * i + 0] = sn0;
    out[3 * i + 1] = sn1;
    out[3 * i + 2] = sn2;
    out[3 * B + i] = r;
}

extern "C" void kernel_launch(void* const* d_in, const int* in_sizes, int n_in,
                              void* d_out, int out_size)
{
    const float* s  = (const float*)d_in[0];
    const float* a  = (const float*)d_in[1];
    const float* W1 = (const float*)d_in[2];
    const float* b1 = (const float*)d_in[3];
    const float* W2 = (const float*)d_in[4];
    const float* b2 = (const float*)d_in[5];
    const float* W3 = (const float*)d_in[6];
    const float* b3 = (const float*)d_in[7];
    float* out = (float*)d_out;

    int B = in_sizes[0] / 3;
    int threads = 128;
    int blocks = (B + threads - 1) / threads;
    dyn_reward_kernel<<<blocks, threads>>>(s, a, W1, b1, W2, b2, W3, b3, out, B);
}

// round 5
// speedup vs baseline: 6.9123x; 6.9123x over previous
#include <cuda_runtime.h>
#include <cuda_fp16.h>
#include <mma.h>
#include <cstdint>

using namespace nvcuda;

#define HID 128
#define NTHREADS 256
#define NGRID 148

// ---------------- SMEM layout (bytes) ----------------
// padded rows: A/W2 rows are 136 halves (272B), C rows are 132 floats (528B)
#define OFF_AH   0                         // half [128][136] = 34816
#define OFF_W2S  34816                     // half [128][136] = 34816
#define OFF_CS   69632                     // float [128][132] = 67584
#define OFF_W1   137216                    // float [5*128]   = 2560
#define OFF_B1   139776                    // float [128]
#define OFF_B2   140288                    // float [128]
#define OFF_B3   140800                    // float [4]
#define OFF_W3   140816                    // float4 [128] = 2048
#define SMEM_TOTAL 142864

#define LDA 136
#define LDC 132

// W2 in fp16 (row-major k x n), prepared once
__device__ __half g_w2h[HID * HID];

__global__ void prep_w2_kernel(const float* __restrict__ W2) {
    int idx = blockIdx.x * blockDim.x + threadIdx.x;
    if (idx < HID * HID) g_w2h[idx] = __float2half(W2[idx]);
}

__global__ __launch_bounds__(NTHREADS, 1)
void dyn_wmma_kernel(const float* __restrict__ s,
                     const float* __restrict__ a,
                     const float* __restrict__ W1,
                     const float* __restrict__ b1,
                     const float* __restrict__ b2,
                     const float* __restrict__ W3,
                     const float* __restrict__ b3,
                     float* __restrict__ out,
                     int B)
{
    extern __shared__ char smem[];
    __half* Ah  = (__half*)(smem + OFF_AH);
    __half* W2s = (__half*)(smem + OFF_W2S);
    float*  Cs  = (float*)(smem + OFF_CS);
    float*  w1s = (float*)(smem + OFF_W1);
    float*  b1s = (float*)(smem + OFF_B1);
    float*  b2s = (float*)(smem + OFF_B2);
    float*  b3s = (float*)(smem + OFF_B3);
    float4* w3p = (float4*)(smem + OFF_W3);

    const int t = threadIdx.x;
    const int wid = t >> 5;

    // ---- prologue: stage W2 (padded rows) + small params ----
    for (int idx = t; idx < HID * (HID / 4); idx += NTHREADS) {
        // copy 4 halves (8B) at a time: row = idx/32, chunk = idx%32
        int row = idx >> 5, c = idx & 31;
        *(uint2*)(W2s + row * LDA + c * 4) = *(const uint2*)(g_w2h + row * HID + c * 4);
    }
    for (int i = t; i < 5 * HID; i += NTHREADS) w1s[i] = W1[i];
    if (t < HID) { b1s[t] = b1[t]; b2s[t] = b2[t]; }
    if (t < 3) b3s[t] = b3[t];
    if (t < HID) w3p[t] = make_float4(W3[3 * t], W3[3 * t + 1], W3[3 * t + 2], 0.0f);
    __syncthreads();

    const int row = t & 127;    // batch row within tile this thread handles (layer1)
    const int half_id = t >> 7; // 0: k cols 0-63, 1: k cols 64-127
    const int ntiles = B / 128;

    for (int tile = blockIdx.x; tile < ntiles; tile += gridDim.x) {
        const int rg = tile * 128 + row;

        // ================= phase 1: layer 1 (fp32 -> fp16 A tile) =================
        const float x0 = s[3 * rg + 0];
        const float x1 = s[3 * rg + 1];
        const float x2 = s[3 * rg + 2];
        const float a0 = a[2 * rg + 0];
        const float a1 = a[2 * rg + 1];

        {
            const int kb = half_id * 64;
#pragma unroll
            for (int g = 0; g < 16; g++) {
                const int k0 = kb + g * 4;
                float4 bb = *(const float4*)(b1s + k0);
                float4 w0 = *(const float4*)(w1s + 0 * HID + k0);
                float4 w1_ = *(const float4*)(w1s + 1 * HID + k0);
                float4 w2_ = *(const float4*)(w1s + 2 * HID + k0);
                float4 w3_ = *(const float4*)(w1s + 3 * HID + k0);
                float4 w4_ = *(const float4*)(w1s + 4 * HID + k0);
                float h0 = bb.x + x0 * w0.x + x1 * w1_.x + x2 * w2_.x + a0 * w3_.x + a1 * w4_.x;
                float h1v = bb.y + x0 * w0.y + x1 * w1_.y + x2 * w2_.y + a0 * w3_.y + a1 * w4_.y;
                float h2 = bb.z + x0 * w0.z + x1 * w1_.z + x2 * w2_.z + a0 * w3_.z + a1 * w4_.z;
                float h3 = bb.w + x0 * w0.w + x1 * w1_.w + x2 * w2_.w + a0 * w3_.w + a1 * w4_.w;
                h0 = fmaxf(h0, 0.0f); h1v = fmaxf(h1v, 0.0f);
                h2 = fmaxf(h2, 0.0f); h3 = fmaxf(h3, 0.0f);
                __half2 p0 = __floats2half2_rn(h0, h1v);
                __half2 p1 = __floats2half2_rn(h2, h3);
                uint2 u;
                u.x = *(uint32_t*)&p0;
                u.y = *(uint32_t*)&p1;
                *(uint2*)(Ah + row * LDA + k0) = u;
            }
        }

        // reward on upper half threads (independent of MLP)
        if (half_id == 1) {
            const float VAR = 0.035f, SIG = 0.03f, TWO_PI = 6.283185307179586f;
            const float ox[6] = {0.f, 0.f, 0.f, 0.f, 0.f, -0.8f};
            const float oy[6] = {0.f, 0.2f, 0.4f, 0.6f, 0.8f, -0.8f};
            float gs = 0.0f;
#pragma unroll
            for (int o = 0; o < 6; o++) {
                float dx = x0 - ox[o], dy = x1 - oy[o];
                gs += expf(-0.5f * (dx * dx + dy * dy) / VAR);
            }
            float gauss_sum = 100.0f * gs / (TWO_PI * VAR);
            float qx = x0 - a0, qy = x1 - a1;
            float quad = 30.0f * (qx * qx + qy * qy);
            float coef = 1.0f / (SIG * sqrtf(TWO_PI));
            float t0 = (x0 + 1.5f) / SIG, t1 = (x0 - 1.5f) / SIG;
            float t2 = (x1 - 1.0f) / SIG, t3 = (x1 + 1.0f) / SIG;
            float bound = 10.0f * coef * (expf(-0.5f * t0 * t0) + expf(-0.5f * t1 * t1) +
                                          expf(-0.5f * t2 * t2) + expf(-0.5f * t3 * t3));
            out[3 * B + rg] = -(quad + gauss_sum + bound);
        }
        __syncthreads();

        // ================= phase 2: tensor-core GEMM h @ W2 =================
        {
            // warp wid owns rows [wid*16, wid*16+16)
            wmma::fragment<wmma::matrix_a, 16, 16, 16, __half, wmma::row_major> afrag[8];
#pragma unroll
            for (int k = 0; k < 8; k++)
                wmma::load_matrix_sync(afrag[k], Ah + (wid * 16) * LDA + k * 16, LDA);

#pragma unroll
            for (int nt = 0; nt < 8; nt++) {
                wmma::fragment<wmma::accumulator, 16, 16, 16, float> cfrag;
                wmma::fill_fragment(cfrag, 0.0f);
#pragma unroll
                for (int k = 0; k < 8; k++) {
                    wmma::fragment<wmma::matrix_b, 16, 16, 16, __half, wmma::row_major> bfrag;
                    wmma::load_matrix_sync(bfrag, W2s + (k * 16) * LDA + nt * 16, LDA);
                    wmma::mma_sync(cfrag, afrag[k], bfrag, cfrag);
                }
                wmma::store_matrix_sync(Cs + (wid * 16) * LDC + nt * 16, cfrag, LDC,
                                        wmma::mem_row_major);
            }
        }
        __syncthreads();

        // ================= phase 3: epilogue +b2, relu, layer 3 (fp32) =================
        if (half_id == 0) {
            const float* crow = Cs + row * LDC;
            float sn0 = b3s[0], sn1 = b3s[1], sn2 = b3s[2];
#pragma unroll
            for (int j = 0; j < HID; j += 4) {
                float4 cv = *(const float4*)(crow + j);
                float4 bb = *(const float4*)(b2s + j);
                float v0 = fmaxf(cv.x + bb.x, 0.0f);
                float v1 = fmaxf(cv.y + bb.y, 0.0f);
                float v2 = fmaxf(cv.z + bb.z, 0.0f);
                float v3 = fmaxf(cv.w + bb.w, 0.0f);
                float4 w0 = w3p[j + 0];
                float4 w1_ = w3p[j + 1];
                float4 w2_ = w3p[j + 2];
                float4 w3_ = w3p[j + 3];
                sn0 = fmaf(v0, w0.x, sn0); sn1 = fmaf(v0, w0.y, sn1); sn2 = fmaf(v0, w0.z, sn2);
                sn0 = fmaf(v1, w1_.x, sn0); sn1 = fmaf(v1, w1_.y, sn1); sn2 = fmaf(v1, w1_.z, sn2);
                sn0 = fmaf(v2, w2_.x, sn0); sn1 = fmaf(v2, w2_.y, sn1); sn2 = fmaf(v2, w2_.z, sn2);
                sn0 = fmaf(v3, w3_.x, sn0); sn1 = fmaf(v3, w3_.y, sn1); sn2 = fmaf(v3, w3_.z, sn2);
            }
            out[3 * rg + 0] = sn0;
            out[3 * rg + 1] = sn1;
            out[3 * rg + 2] = sn2;
        }
        __syncthreads();   // protect Ah / Cs before next tile overwrites them
    }
}

extern "C" void kernel_launch(void* const* d_in, const int* in_sizes, int n_in,
                              void* d_out, int out_size)
{
    const float* s  = (const float*)d_in[0];
    const float* a  = (const float*)d_in[1];
    const float* W1 = (const float*)d_in[2];
    const float* b1 = (const float*)d_in[3];
    const float* W2 = (const float*)d_in[4];
    const float* b2 = (const float*)d_in[5];
    const float* W3 = (const float*)d_in[6];
    const float* b3 = (const float*)d_in[7];
    float* out = (float*)d_out;

    int B = in_sizes[0] / 3;

    prep_w2_kernel<<<(HID * HID + 255) / 256, 256>>>(W2);

    cudaFuncSetAttribute(dyn_wmma_kernel,
                         cudaFuncAttributeMaxDynamicSharedMemorySize, SMEM_TOTAL);
    dyn_wmma_kernel<<<NGRID, NTHREADS, SMEM_TOTAL>>>(s, a, W1, b1, b2, W3, b3, out, B);
}